// round 5
// baseline (speedup 1.0000x reference)
#include <cuda_runtime.h>

#define B_DIM 256
#define T_DIM 64
#define D_DIM 2048
#define THRESHOLD 0.99f
#define EPSILON 0.01f

#define THREADS 256
#define HALF_THREADS 128
#define D4 (D_DIM / 4)                    // 512 float4 per row
#define BLOCKS_PER_B (D4 / HALF_THREADS)  // 4
#define T_HALF (T_DIM / 2)                // 32

// ---------------------------------------------------------------------------
// Fused kernel, block-internal T-split, fully unrolled T-loop for deep MLP.
// grid = B*4, block = 256.
//   threads [0,128)  : reduce t in [0,32)  over 128 float4 columns
//   threads [128,256): reduce t in [32,64) over the same columns
// __launch_bounds__(256, 4) -> up to 64 regs/thread so ptxas can front-batch
// loads (documented MLP_eff ~16 at unroll 32).
// ---------------------------------------------------------------------------
__global__ __launch_bounds__(THREADS, 4)
void act_fused_kernel(const float* __restrict__ halt_probs,   // [B,T]
                      const float* __restrict__ outputs,      // [B,T,D]
                      const float* __restrict__ step_weights, // [B,T]
                      float* __restrict__ final_out,          // [B,D]
                      float* __restrict__ out_ponder,         // [B]
                      float* __restrict__ out_weights)        // [B,T]
{
    const int b     = blockIdx.x / BLOCKS_PER_B;
    const int chunk = blockIdx.x % BLOCKS_PER_B;
    const int tid   = threadIdx.x;
    const int half  = tid >> 7;          // 0 or 1
    const int lane  = tid & (HALF_THREADS - 1);

    __shared__ float  sp[T_DIM];
    __shared__ float  wsh[T_DIM];
    __shared__ int    s_h;
    __shared__ float  s_rem;
    __shared__ float  s_wsum;
    __shared__ float4 s_part[HALF_THREADS];   // 2 KB

    // ---- prologue: halting weights for batch b ----
    if (tid < T_DIM) sp[tid] = halt_probs[b * T_DIM + tid];
    __syncthreads();

    if (tid == 0) {
        float cum = 0.0f;
        int   h   = T_DIM - 1;
        bool  found = false;
        #pragma unroll
        for (int i = 0; i < T_DIM; i++) {
            cum += sp[i];
            if (!found && cum >= THRESHOLD) { found = true; h = i; }
        }
        float cum_at = 0.0f;
        for (int i = 0; i <= h; i++) cum_at += sp[i];
        s_h   = h;
        s_rem = 1.0f - cum_at + sp[h];
    }
    __syncthreads();

    const int   h   = s_h;
    const float rem = s_rem;

    if (tid < T_DIM) {
        float w = (tid < h) ? sp[tid] : ((tid == h) ? rem : 0.0f);
        w *= step_weights[b * T_DIM + tid];
        wsh[tid] = w;
    }
    __syncthreads();

    if (tid == 0) {
        float s = 0.0f;
        #pragma unroll
        for (int i = 0; i < T_DIM; i++) s += wsh[i];
        s_wsum = fmaxf(s, EPSILON);
    }
    __syncthreads();

    const float inv_wsum = 1.0f / s_wsum;
    if (tid < T_DIM) wsh[tid] *= inv_wsum;
    __syncthreads();

    if (chunk == 0) {
        if (tid < T_DIM) out_weights[b * T_DIM + tid] = wsh[tid];
        if (tid == 0) {
            float pc = 0.0f;
            #pragma unroll
            for (int i = 0; i < T_DIM; i++) pc += wsh[i] * (float)(i + 1);
            out_ponder[b] = pc;
        }
    }

    // ---- weighted reduction over this half's 32 t-steps, fully unrolled ----
    const int d4     = chunk * HALF_THREADS + lane;   // float4 col in [0, D4)
    const int t_base = half * T_HALF;

    const float4* __restrict__ base =
        reinterpret_cast<const float4*>(outputs)
        + (size_t)b * T_DIM * D4 + (size_t)t_base * D4 + d4;

    float4 acc = make_float4(0.f, 0.f, 0.f, 0.f);

    #pragma unroll
    for (int t = 0; t < T_HALF; t++) {
        const float4 v = __ldcs(base + (size_t)t * D4);
        const float  w = wsh[t_base + t];
        acc.x = fmaf(w, v.x, acc.x);
        acc.y = fmaf(w, v.y, acc.y);
        acc.z = fmaf(w, v.z, acc.z);
        acc.w = fmaf(w, v.w, acc.w);
    }

    // ---- combine halves through shared, single store ----
    if (half == 1) s_part[lane] = acc;
    __syncthreads();
    if (half == 0) {
        const float4 o = s_part[lane];
        acc.x += o.x; acc.y += o.y; acc.z += o.z; acc.w += o.w;
        reinterpret_cast<float4*>(final_out)[(size_t)b * D4 + d4] = acc;
    }
}

// ---------------------------------------------------------------------------
// kernel_launch
// Inputs: halt_probs [B,T,1], outputs [B,T,D], step_weights [B,T]  (fp32)
// Output: concat(final_output [B*D], ponder_cost [B], weights [B*T]) fp32
// ---------------------------------------------------------------------------
extern "C" void kernel_launch(void* const* d_in, const int* in_sizes, int n_in,
                              void* d_out, int out_size)
{
    const float* halt_probs   = (const float*)d_in[0];
    const float* outputs      = (const float*)d_in[1];
    const float* step_weights = (const float*)d_in[2];

    float* out         = (float*)d_out;
    float* final_out   = out;                              // [B,D]
    float* ponder_out  = out + (size_t)B_DIM * D_DIM;      // [B]
    float* weights_out = ponder_out + B_DIM;               // [B,T]

    act_fused_kernel<<<B_DIM * BLOCKS_PER_B, THREADS>>>(
        halt_probs, outputs, step_weights,
        final_out, ponder_out, weights_out);
}

// round 7
// speedup vs baseline: 3.9767x; 3.9767x over previous
#include <cuda_runtime.h>

#define B_DIM 256
#define T_DIM 64
#define D_DIM 2048
#define THRESHOLD 0.99f
#define EPSILON 0.01f

#define THREADS 128
#define D4 (D_DIM / 4)                    // 512 float4 per row
#define BLOCKS_PER_B 4                    // 4 chunks of 128 float4 columns
#define PF 4                              // prefetch depth (covers h<=3: ~96%)

// ---------------------------------------------------------------------------
// Fused ACT kernel exploiting weight sparsity: weights[t] == 0 for t > h,
// and h ~ 2-3 for U(0,1) halt probs. Only rows t <= h are loaded (plus a
// fixed 4-row prefetch issued before the weight prologue to hide latency).
// grid = B*4, block = 128. Warp 0 computes the halting weights with a
// shuffle scan; all threads prefetch rows 0..3 concurrently.
// ---------------------------------------------------------------------------
__global__ __launch_bounds__(THREADS)
void act_sparse_kernel(const float* __restrict__ halt_probs,   // [B,T]
                       const float* __restrict__ outputs,      // [B,T,D]
                       const float* __restrict__ step_weights, // [B,T]
                       float* __restrict__ final_out,          // [B,D]
                       float* __restrict__ out_ponder,         // [B]
                       float* __restrict__ out_weights)        // [B,T]
{
    const int b     = blockIdx.x / BLOCKS_PER_B;
    const int chunk = blockIdx.x % BLOCKS_PER_B;
    const int tid   = threadIdx.x;
    const int warp  = tid >> 5;
    const int lane  = tid & 31;
    const unsigned FULL = 0xFFFFFFFFu;

    __shared__ float wsh[T_DIM];
    __shared__ int   sh_h;

    const int d4 = chunk * THREADS + tid;   // float4 column in [0, D4)
    const float4* __restrict__ base =
        reinterpret_cast<const float4*>(outputs) + (size_t)b * T_DIM * D4 + d4;

    // ---- prefetch first PF rows (independent of weights) ----
    float4 v0 = __ldcs(base + 0 * D4);
    float4 v1 = __ldcs(base + 1 * D4);
    float4 v2 = __ldcs(base + 2 * D4);
    float4 v3 = __ldcs(base + 3 * D4);

    // ---- warp 0: halting weights via shuffle scan (overlaps prefetch) ----
    if (warp == 0) {
        // lane owns t = 2*lane, 2*lane+1
        const float2 p  = reinterpret_cast<const float2*>(halt_probs  + b * T_DIM)[lane];
        const float2 sw = reinterpret_cast<const float2*>(step_weights + b * T_DIM)[lane];

        // inclusive scan of pair sums
        const float pairsum = p.x + p.y;
        float s = pairsum;
        #pragma unroll
        for (int o = 1; o < 32; o <<= 1) {
            float n = __shfl_up_sync(FULL, s, o);
            if (lane >= o) s += n;
        }
        const float excl = s - pairsum;     // cumsum before t=2*lane
        const float cum0 = excl + p.x;      // cumsum at t=2*lane
        const float cum1 = s;               // cumsum at t=2*lane+1

        const unsigned m0 = __ballot_sync(FULL, cum0 >= THRESHOLD);
        const unsigned m1 = __ballot_sync(FULL, cum1 >= THRESHOLD);
        const int c0 = m0 ? 2 * (__ffs(m0) - 1)     : T_DIM;
        const int c1 = m1 ? 2 * (__ffs(m1) - 1) + 1 : T_DIM;
        int h = min(c0, c1);
        if (h >= T_DIM) h = T_DIM - 1;

        const int   hl   = h >> 1;
        const int   hodd = h & 1;
        const float cum_at = __shfl_sync(FULL, hodd ? cum1 : cum0, hl);
        const float p_at   = __shfl_sync(FULL, hodd ? p.y  : p.x,  hl);
        const float rem    = 1.0f - cum_at + p_at;

        const int t0i = 2 * lane, t1i = 2 * lane + 1;
        float w0 = (t0i < h) ? p.x : ((t0i == h) ? rem : 0.0f);
        float w1 = (t1i < h) ? p.y : ((t1i == h) ? rem : 0.0f);
        w0 *= sw.x; w1 *= sw.y;

        float ws = w0 + w1;
        #pragma unroll
        for (int o = 16; o; o >>= 1) ws += __shfl_xor_sync(FULL, ws, o);
        const float inv = 1.0f / fmaxf(ws, EPSILON);
        w0 *= inv; w1 *= inv;

        reinterpret_cast<float2*>(wsh)[lane] = make_float2(w0, w1);
        if (lane == 0) sh_h = h;

        if (chunk == 0) {
            reinterpret_cast<float2*>(out_weights + b * T_DIM)[lane] =
                make_float2(w0, w1);
            float pc = w0 * (float)(t0i + 1) + w1 * (float)(t1i + 1);
            #pragma unroll
            for (int o = 16; o; o >>= 1) pc += __shfl_xor_sync(FULL, pc, o);
            if (lane == 0) out_ponder[b] = pc;
        }
    }
    __syncthreads();

    const int h = sh_h;

    // ---- consume prefetched rows (weights may be zero beyond h: exact) ----
    float4 acc;
    {
        const float w0 = wsh[0], w1 = wsh[1], w2 = wsh[2], w3 = wsh[3];
        acc.x = w0 * v0.x; acc.y = w0 * v0.y; acc.z = w0 * v0.z; acc.w = w0 * v0.w;
        acc.x = fmaf(w1, v1.x, acc.x); acc.y = fmaf(w1, v1.y, acc.y);
        acc.z = fmaf(w1, v1.z, acc.z); acc.w = fmaf(w1, v1.w, acc.w);
        acc.x = fmaf(w2, v2.x, acc.x); acc.y = fmaf(w2, v2.y, acc.y);
        acc.z = fmaf(w2, v2.z, acc.z); acc.w = fmaf(w2, v2.w, acc.w);
        acc.x = fmaf(w3, v3.x, acc.x); acc.y = fmaf(w3, v3.y, acc.y);
        acc.z = fmaf(w3, v3.z, acc.z); acc.w = fmaf(w3, v3.w, acc.w);
    }

    // ---- rare tail: h >= PF (~4% of batches), batched guarded loads ----
    for (int t0 = PF; t0 <= h; t0 += 4) {
        float4 u[4];
        #pragma unroll
        for (int i = 0; i < 4; i++) {
            const int t = t0 + i;
            u[i] = (t < T_DIM) ? __ldcs(base + (size_t)t * D4)
                               : make_float4(0.f, 0.f, 0.f, 0.f);
        }
        #pragma unroll
        for (int i = 0; i < 4; i++) {
            const int t = t0 + i;
            const float w = (t < T_DIM) ? wsh[t] : 0.0f;
            acc.x = fmaf(w, u[i].x, acc.x);
            acc.y = fmaf(w, u[i].y, acc.y);
            acc.z = fmaf(w, u[i].z, acc.z);
            acc.w = fmaf(w, u[i].w, acc.w);
        }
    }

    reinterpret_cast<float4*>(final_out)[(size_t)b * D4 + d4] = acc;
}

// ---------------------------------------------------------------------------
// kernel_launch
// Inputs: halt_probs [B,T,1], outputs [B,T,D], step_weights [B,T]  (fp32)
// Output: concat(final_output [B*D], ponder_cost [B], weights [B*T]) fp32
// ---------------------------------------------------------------------------
extern "C" void kernel_launch(void* const* d_in, const int* in_sizes, int n_in,
                              void* d_out, int out_size)
{
    const float* halt_probs   = (const float*)d_in[0];
    const float* outputs      = (const float*)d_in[1];
    const float* step_weights = (const float*)d_in[2];

    float* out         = (float*)d_out;
    float* final_out   = out;                              // [B,D]
    float* ponder_out  = out + (size_t)B_DIM * D_DIM;      // [B]
    float* weights_out = ponder_out + B_DIM;               // [B,T]

    act_sparse_kernel<<<B_DIM * BLOCKS_PER_B, THREADS>>>(
        halt_probs, outputs, step_weights,
        final_out, ponder_out, weights_out);
}

// round 8
// speedup vs baseline: 4.1304x; 1.0386x over previous
#include <cuda_runtime.h>

#define B_DIM 256
#define T_DIM 64
#define D_DIM 2048
#define THRESHOLD 0.99f
#define EPSILON 0.01f

#define THREADS 128
#define D4 (D_DIM / 4)                    // 512 float4 per row
#define BLOCKS_PER_B 4                    // 4 chunks of 128 float4 columns
#define PF 4                              // prefetch depth (covers h<=3: ~96%)

// ---------------------------------------------------------------------------
// Sparse ACT kernel, barrier-free: weights[t]==0 for t>h and h~2-3 for
// U(0,1) halt probs, so only rows t<=h are needed. Each WARP redundantly
// computes the halting weights with a shuffle scan (no smem, no
// __syncthreads), overlapped with the 4-row prefetch. Tail (h>=4) is rare.
// grid = B*4, block = 128.
// ---------------------------------------------------------------------------
__global__ __launch_bounds__(THREADS)
void act_sparse_kernel(const float* __restrict__ halt_probs,   // [B,T]
                       const float* __restrict__ outputs,      // [B,T,D]
                       const float* __restrict__ step_weights, // [B,T]
                       float* __restrict__ final_out,          // [B,D]
                       float* __restrict__ out_ponder,         // [B]
                       float* __restrict__ out_weights)        // [B,T]
{
    const int b     = blockIdx.x / BLOCKS_PER_B;
    const int chunk = blockIdx.x % BLOCKS_PER_B;
    const int tid   = threadIdx.x;
    const int warp  = tid >> 5;
    const int lane  = tid & 31;
    const unsigned FULL = 0xFFFFFFFFu;

    const int d4 = chunk * THREADS + tid;   // float4 column in [0, D4)
    const float4* __restrict__ base =
        reinterpret_cast<const float4*>(outputs) + (size_t)b * T_DIM * D4 + d4;

    // ---- issue row prefetch FIRST (independent of weights) ----
    float4 v0 = __ldcs(base + 0 * D4);
    float4 v1 = __ldcs(base + 1 * D4);
    float4 v2 = __ldcs(base + 2 * D4);
    float4 v3 = __ldcs(base + 3 * D4);

    // ---- per-warp redundant weight computation (overlaps row loads) ----
    // lane owns t = 2*lane, 2*lane+1
    const float2 p  = reinterpret_cast<const float2*>(halt_probs   + b * T_DIM)[lane];
    const float2 sw = reinterpret_cast<const float2*>(step_weights + b * T_DIM)[lane];

    // inclusive scan of pair sums
    const float pairsum = p.x + p.y;
    float s = pairsum;
    #pragma unroll
    for (int o = 1; o < 32; o <<= 1) {
        float n = __shfl_up_sync(FULL, s, o);
        if (lane >= o) s += n;
    }
    const float excl = s - pairsum;     // cumsum before t=2*lane
    const float cum0 = excl + p.x;      // cumsum at t=2*lane
    const float cum1 = s;               // cumsum at t=2*lane+1

    const unsigned m0 = __ballot_sync(FULL, cum0 >= THRESHOLD);
    const unsigned m1 = __ballot_sync(FULL, cum1 >= THRESHOLD);
    const int c0 = m0 ? 2 * (__ffs(m0) - 1)     : T_DIM;
    const int c1 = m1 ? 2 * (__ffs(m1) - 1) + 1 : T_DIM;
    int h = min(c0, c1);
    if (h >= T_DIM) h = T_DIM - 1;

    const int   hl   = h >> 1;
    const int   hodd = h & 1;
    const float cum_at = __shfl_sync(FULL, hodd ? cum1 : cum0, hl);
    const float p_at   = __shfl_sync(FULL, hodd ? p.y  : p.x,  hl);
    const float rem    = 1.0f - cum_at + p_at;

    const int t0i = 2 * lane, t1i = 2 * lane + 1;
    float w0 = (t0i < h) ? p.x : ((t0i == h) ? rem : 0.0f);
    float w1 = (t1i < h) ? p.y : ((t1i == h) ? rem : 0.0f);
    w0 *= sw.x; w1 *= sw.y;

    float ws = w0 + w1;
    #pragma unroll
    for (int o = 16; o; o >>= 1) ws += __shfl_xor_sync(FULL, ws, o);
    const float inv = 1.0f / fmaxf(ws, EPSILON);
    w0 *= inv; w1 *= inv;

    // weights + ponder outputs: one warp of one block per batch
    if (chunk == 0 && warp == 0) {
        reinterpret_cast<float2*>(out_weights + b * T_DIM)[lane] =
            make_float2(w0, w1);
        float pc = w0 * (float)(t0i + 1) + w1 * (float)(t1i + 1);
        #pragma unroll
        for (int o = 16; o; o >>= 1) pc += __shfl_xor_sync(FULL, pc, o);
        if (lane == 0) out_ponder[b] = pc;
    }

    // broadcast first-4 weights from lanes 0,1
    const float wa = __shfl_sync(FULL, w0, 0);   // t=0
    const float wb = __shfl_sync(FULL, w1, 0);   // t=1
    const float wc = __shfl_sync(FULL, w0, 1);   // t=2
    const float wd = __shfl_sync(FULL, w1, 1);   // t=3

    // ---- consume prefetched rows ----
    float4 acc;
    acc.x = wa * v0.x; acc.y = wa * v0.y; acc.z = wa * v0.z; acc.w = wa * v0.w;
    acc.x = fmaf(wb, v1.x, acc.x); acc.y = fmaf(wb, v1.y, acc.y);
    acc.z = fmaf(wb, v1.z, acc.z); acc.w = fmaf(wb, v1.w, acc.w);
    acc.x = fmaf(wc, v2.x, acc.x); acc.y = fmaf(wc, v2.y, acc.y);
    acc.z = fmaf(wc, v2.z, acc.z); acc.w = fmaf(wc, v2.w, acc.w);
    acc.x = fmaf(wd, v3.x, acc.x); acc.y = fmaf(wd, v3.y, acc.y);
    acc.z = fmaf(wd, v3.z, acc.z); acc.w = fmaf(wd, v3.w, acc.w);

    // ---- rare tail: h >= PF (~4% of batches), batched guarded loads ----
    for (int t0 = PF; t0 <= h; t0 += 4) {
        float4 u[4];
        #pragma unroll
        for (int i = 0; i < 4; i++) {
            const int t = t0 + i;
            u[i] = (t < T_DIM) ? __ldcs(base + (size_t)t * D4)
                               : make_float4(0.f, 0.f, 0.f, 0.f);
        }
        #pragma unroll
        for (int i = 0; i < 4; i++) {
            const int t = t0 + i;
            // t is warp-uniform: fetch weight from owning lane
            float wt = __shfl_sync(FULL, (t & 1) ? w1 : w0, (t >> 1) & 31);
            if (t >= T_DIM) wt = 0.0f;
            acc.x = fmaf(wt, u[i].x, acc.x);
            acc.y = fmaf(wt, u[i].y, acc.y);
            acc.z = fmaf(wt, u[i].z, acc.z);
            acc.w = fmaf(wt, u[i].w, acc.w);
        }
    }

    reinterpret_cast<float4*>(final_out)[(size_t)b * D4 + d4] = acc;
}

// ---------------------------------------------------------------------------
// kernel_launch
// Inputs: halt_probs [B,T,1], outputs [B,T,D], step_weights [B,T]  (fp32)
// Output: concat(final_output [B*D], ponder_cost [B], weights [B*T]) fp32
// ---------------------------------------------------------------------------
extern "C" void kernel_launch(void* const* d_in, const int* in_sizes, int n_in,
                              void* d_out, int out_size)
{
    const float* halt_probs   = (const float*)d_in[0];
    const float* outputs      = (const float*)d_in[1];
    const float* step_weights = (const float*)d_in[2];

    float* out         = (float*)d_out;
    float* final_out   = out;                              // [B,D]
    float* ponder_out  = out + (size_t)B_DIM * D_DIM;      // [B]
    float* weights_out = ponder_out + B_DIM;               // [B,T]

    act_sparse_kernel<<<B_DIM * BLOCKS_PER_B, THREADS>>>(
        halt_probs, outputs, step_weights,
        final_out, ponder_out, weights_out);
}